// round 12
// baseline (speedup 1.0000x reference)
#include <cuda_runtime.h>
#include <cuda_bf16.h>
#include <math.h>

#define NTOK 200704          // 64*56*56
#define QKVD 768
#define CDIM 256

// ------------------------- device scratch (no allocs allowed) --------------
__device__ float          g_qkv[(size_t)NTOK * QKVD];   // fp32 qkv for attention
__device__ __nv_bfloat16  g_xh[(size_t)NTOK * CDIM];    // x split hi
__device__ __nv_bfloat16  g_xl[(size_t)NTOK * CDIM];    // x split lo
__device__ __nv_bfloat16  g_ath[(size_t)NTOK * CDIM];   // attention out hi
__device__ __nv_bfloat16  g_atl[(size_t)NTOK * CDIM];   // attention out lo
__device__ __nv_bfloat16  g_wqh[(size_t)QKVD * CDIM];   // w_qkv^T split hi  [N][K]
__device__ __nv_bfloat16  g_wql[(size_t)QKVD * CDIM];
__device__ __nv_bfloat16  g_woh[(size_t)CDIM * CDIM];   // w_out^T split hi  [N][K]
__device__ __nv_bfloat16  g_wol[(size_t)CDIM * CDIM];

// ------------------------- helpers -----------------------------------------
__device__ __forceinline__ unsigned su32(const void* p) {
  return (unsigned)__cvta_generic_to_shared(p);
}
__device__ __forceinline__ void cp16(unsigned s, const void* g) {
  asm volatile("cp.async.cg.shared.global [%0], [%1], 16;\n" ::"r"(s), "l"(g));
}
__device__ __forceinline__ void cp_commit() {
  asm volatile("cp.async.commit_group;\n");
}
template <int N>
__device__ __forceinline__ void cp_wait() {
  asm volatile("cp.async.wait_group %0;\n" ::"n"(N));
}
__device__ __forceinline__ void ldm4(unsigned a, unsigned& r0, unsigned& r1,
                                     unsigned& r2, unsigned& r3) {
  asm volatile(
      "ldmatrix.sync.aligned.m8n8.x4.shared.b16 {%0,%1,%2,%3}, [%4];\n"
      : "=r"(r0), "=r"(r1), "=r"(r2), "=r"(r3)
      : "r"(a));
}
__device__ __forceinline__ void mma16816(float* c, const unsigned* a,
                                         unsigned b0, unsigned b1) {
  asm volatile(
      "mma.sync.aligned.m16n8k16.row.col.f32.bf16.bf16.f32 "
      "{%0,%1,%2,%3},{%4,%5,%6,%7},{%8,%9},{%0,%1,%2,%3};\n"
      : "+f"(c[0]), "+f"(c[1]), "+f"(c[2]), "+f"(c[3])
      : "r"(a[0]), "r"(a[1]), "r"(a[2]), "r"(a[3]), "r"(b0), "r"(b1));
}
__device__ __forceinline__ void split1(float v, __nv_bfloat16& h,
                                       __nv_bfloat16& l) {
  h = __float2bfloat16(v);
  l = __float2bfloat16(v - __bfloat162float(h));
}
// split two floats -> packed bf16x2 hi-pair and lo-pair (elem order: a=low)
__device__ __forceinline__ void splitpack(float a, float b, unsigned& h,
                                          unsigned& l) {
  __nv_bfloat16 ah = __float2bfloat16(a), bh = __float2bfloat16(b);
  __nv_bfloat16 al = __float2bfloat16(a - __bfloat162float(ah));
  __nv_bfloat16 bl = __float2bfloat16(b - __bfloat162float(bh));
  __nv_bfloat162 hh(ah, bh), ll(al, bl);
  h = *reinterpret_cast<unsigned*>(&hh);
  l = *reinterpret_cast<unsigned*>(&ll);
}

// ------------------------- split kernels ------------------------------------
__global__ void split_act(const float* __restrict__ in,
                          __nv_bfloat16* __restrict__ h,
                          __nv_bfloat16* __restrict__ l, size_t n4) {
  size_t i = (size_t)blockIdx.x * blockDim.x + threadIdx.x;
  if (i >= n4) return;
  float4 v = reinterpret_cast<const float4*>(in)[i];
  __nv_bfloat16 h0, h1, h2, h3, l0, l1, l2, l3;
  split1(v.x, h0, l0); split1(v.y, h1, l1);
  split1(v.z, h2, l2); split1(v.w, h3, l3);
  __nv_bfloat162* hp = reinterpret_cast<__nv_bfloat162*>(h) + 2 * i;
  __nv_bfloat162* lp = reinterpret_cast<__nv_bfloat162*>(l) + 2 * i;
  hp[0] = __nv_bfloat162(h0, h1); hp[1] = __nv_bfloat162(h2, h3);
  lp[0] = __nv_bfloat162(l0, l1); lp[1] = __nv_bfloat162(l2, l3);
}

// w[K][N] row-major -> h/l[N][K] (k contiguous)
__global__ void split_wT(const float* __restrict__ w,
                         __nv_bfloat16* __restrict__ h,
                         __nv_bfloat16* __restrict__ l, int K, int N) {
  int idx = blockIdx.x * 256 + threadIdx.x;
  if (idx >= K * N) return;
  int n = idx / K, k = idx - n * K;
  float v = w[(size_t)k * N + n];
  __nv_bfloat16 hh, ll;
  split1(v, hh, ll);
  h[idx] = hh; l[idx] = ll;
}

// ------------------------- split-bf16 tensor-core GEMM (R8, known-good) -----
#define PLANE_B (128 * 64)              // 8192 bytes per plane
#define STAGE_B (4 * PLANE_B)           // 32768 bytes per stage
#define NSTAGE 3

__device__ __forceinline__ unsigned swz(int row, int chunk) {
  return (unsigned)(row * 64 + ((chunk ^ ((row >> 1) & 3)) << 4));
}

__global__ void __launch_bounds__(256) gemm_split(
    const __nv_bfloat16* __restrict__ Ah, const __nv_bfloat16* __restrict__ Al,
    const __nv_bfloat16* __restrict__ Bh, const __nv_bfloat16* __restrict__ Bl,
    const float* __restrict__ bias, float* __restrict__ C, int M, int N,
    int K) {
  extern __shared__ __align__(16) char smem[];
  const unsigned sbase = su32(smem);
  const int tid = threadIdx.x;
  const int lane = tid & 31;
  const int warp = tid >> 5;
  const int wm = warp & 1;
  const int wn = warp >> 1;
  const int bm = blockIdx.y * 128;
  const int bn = blockIdx.x * 128;

  const __nv_bfloat16* gsrc[4] = {Ah + (size_t)bm * K, Al + (size_t)bm * K,
                                  Bh + (size_t)bn * K, Bl + (size_t)bn * K};

  float acc[4][4][4];
#pragma unroll
  for (int i = 0; i < 4; ++i)
#pragma unroll
    for (int j = 0; j < 4; ++j)
#pragma unroll
      for (int r = 0; r < 4; ++r) acc[i][j][r] = 0.f;

  const int NK = K >> 5;  // BK = 32

  auto load_stage = [&](int it, int buf) {
    const int k0 = it << 5;
    const unsigned sb = sbase + buf * STAGE_B;
#pragma unroll
    for (int a = 0; a < 4; ++a) {
      const __nv_bfloat16* g = gsrc[a];
#pragma unroll
      for (int w = 0; w < 2; ++w) {
        int chunk = tid + (w << 8);
        int row = chunk >> 2, kc = chunk & 3;
        cp16(sb + a * PLANE_B + swz(row, kc),
             g + (size_t)row * K + k0 + kc * 8);
      }
    }
  };

  load_stage(0, 0);
  cp_commit();
  load_stage(1, 1);
  cp_commit();

  for (int it = 0; it < NK; ++it) {
    const int buf = it % NSTAGE;
    if (it >= NK - 2) {
      cp_wait<0>();
    } else {
      cp_wait<1>();
    }
    __syncthreads();

    const unsigned sb = sbase + buf * STAGE_B;
#pragma unroll
    for (int kc = 0; kc < 2; ++kc) {
      unsigned bh[2][4], bl[2][4];
      const int grp = lane >> 3;
      const int nrow0 = wn * 32 + ((grp >> 1) << 3) + (lane & 7);
      const int chunkB = (kc << 1) + (grp & 1);
#pragma unroll
      for (int p = 0; p < 2; ++p) {
        const unsigned off = swz(nrow0 + (p << 4), chunkB);
        ldm4(sb + 2 * PLANE_B + off, bh[p][0], bh[p][1], bh[p][2], bh[p][3]);
        ldm4(sb + 3 * PLANE_B + off, bl[p][0], bl[p][1], bl[p][2], bl[p][3]);
      }
      const int ar = wm * 64 + (lane & 15);
      const int chunkA = (kc << 1) + (lane >> 4);
#pragma unroll
      for (int mt = 0; mt < 4; ++mt) {
        unsigned ah[4], al[4];
        const unsigned aoff = swz(ar + (mt << 4), chunkA);
        ldm4(sb + aoff, ah[0], ah[1], ah[2], ah[3]);
        ldm4(sb + PLANE_B + aoff, al[0], al[1], al[2], al[3]);
#pragma unroll
        for (int nt = 0; nt < 4; ++nt) {
          unsigned b0h = bh[nt >> 1][(nt & 1) * 2], b1h = bh[nt >> 1][(nt & 1) * 2 + 1];
          unsigned b0l = bl[nt >> 1][(nt & 1) * 2], b1l = bl[nt >> 1][(nt & 1) * 2 + 1];
          mma16816(acc[mt][nt], ah, b0h, b1h);
          mma16816(acc[mt][nt], ah, b0l, b1l);
          mma16816(acc[mt][nt], al, b0h, b1h);
        }
      }
    }

    if (it + 2 < NK) {
      load_stage(it + 2, (it + 2) % NSTAGE);
      cp_commit();
    }
  }

#pragma unroll
  for (int mt = 0; mt < 4; ++mt) {
    const int row = bm + wm * 64 + mt * 16 + (lane >> 2);
#pragma unroll
    for (int nt = 0; nt < 4; ++nt) {
      const int col = bn + wn * 32 + nt * 8 + (lane & 3) * 2;
      const float b0 = bias[col], b1 = bias[col + 1];
      float2 o0 = {acc[mt][nt][0] + b0, acc[mt][nt][1] + b1};
      float2 o1 = {acc[mt][nt][2] + b0, acc[mt][nt][3] + b1};
      *reinterpret_cast<float2*>(&C[(size_t)row * N + col]) = o0;
      *reinterpret_cast<float2*>(&C[(size_t)(row + 8) * N + col]) = o1;
    }
  }
}

// ------------------------- tensor-core windowed attention -------------------
// One CTA per (window, head), 128 threads = 4 warps. Warp w owns M-rows
// [w*16, w*16+16). Scores (64x56 padded, bf16 3-term HMMA) accumulate in
// registers; softmax + P-split in registers (C-frag layout == A-frag layout);
// PV (K=56 padded to 64) via HMMA with transposed V.
#define QP2 40   // q pitch (bf16)
#define KP2 40   // k pitch
#define VP2 72   // vT pitch

__global__ void __launch_bounds__(128) win_attn(const float* __restrict__ pos) {
  __shared__ __nv_bfloat16 sqh[64 * QP2], sql[64 * QP2];
  __shared__ __nv_bfloat16 skh[56 * KP2], skl[56 * KP2];
  __shared__ __nv_bfloat16 svh[32 * VP2], svl[32 * VP2];
  __shared__ float sp[169];
  __shared__ int bidx[64];

  const int tid = threadIdx.x;
  const int lane = tid & 31;
  const int warp = tid >> 5;
  const int g = lane >> 2;       // group 0..7
  const int th = lane & 3;       // thread-in-group
  const int win = blockIdx.x;
  const int head = blockIdx.y;
  const int b = win >> 6;
  const int wi = (win >> 3) & 7;
  const int wj = win & 7;
  const long rowbase = ((long)(b * 56 + wi * 7)) * 56 + wj * 7;
  const float scale = 5.656854249492380195f;  // sqrt(32), reference multiplies

  for (int i = tid; i < 169; i += 128) sp[i] = pos[i];
  if (tid < 64) bidx[tid] = (tid < 49) ? (tid / 7 + tid % 7) : 0;
  // zero pads: k rows 49..55 (cols 0..31), vT cols 49..63 (all 32 d-rows)
  const __nv_bfloat16 z = __float2bfloat16(0.f);
  for (int i = tid; i < 7 * 32; i += 128) {
    int r = 49 + i / 32, c = i % 32;
    skh[r * KP2 + c] = z; skl[r * KP2 + c] = z;
  }
  for (int i = tid; i < 32 * 15; i += 128) {
    int d = i / 15, l = 49 + i % 15;
    svh[d * VP2 + l] = z; svl[d * VP2 + l] = z;
  }
  // zero q pad rows 49..63 (avoid NaN garbage feeding exp)
  for (int i = tid; i < 15 * 32; i += 128) {
    int r = 49 + i / 32, c = i % 32;
    sqh[r * QP2 + c] = z; sql[r * QP2 + c] = z;
  }
  for (int i = tid; i < 49 * 32; i += 128) {
    const int t = i >> 5, d = i & 31;
    const long grow = rowbase + (t / 7) * 56 + (t % 7);
    const float* p = &g_qkv[grow * 768 + head * 32 + d];
    __nv_bfloat16 hh, ll;
    split1(p[0] * scale, hh, ll);         // fold sqrt(32) into q
    sqh[t * QP2 + d] = hh; sql[t * QP2 + d] = ll;
    split1(p[256], hh, ll);
    skh[t * KP2 + d] = hh; skl[t * KP2 + d] = ll;
    split1(p[512], hh, ll);
    svh[d * VP2 + t] = hh; svl[d * VP2 + t] = ll;   // transposed [d][l]
  }
  __syncthreads();

  // ---- A fragments (q) for both k-halves, hi+lo ----
  unsigned aqh[2][4], aql[2][4];
  {
    const int row = warp * 16 + g;
#pragma unroll
    for (int kh = 0; kh < 2; ++kh) {
      const int c = kh * 16 + th * 2;
      aqh[kh][0] = *reinterpret_cast<const unsigned*>(&sqh[row * QP2 + c]);
      aqh[kh][1] = *reinterpret_cast<const unsigned*>(&sqh[(row + 8) * QP2 + c]);
      aqh[kh][2] = *reinterpret_cast<const unsigned*>(&sqh[row * QP2 + c + 8]);
      aqh[kh][3] = *reinterpret_cast<const unsigned*>(&sqh[(row + 8) * QP2 + c + 8]);
      aql[kh][0] = *reinterpret_cast<const unsigned*>(&sql[row * QP2 + c]);
      aql[kh][1] = *reinterpret_cast<const unsigned*>(&sql[(row + 8) * QP2 + c]);
      aql[kh][2] = *reinterpret_cast<const unsigned*>(&sql[row * QP2 + c + 8]);
      aql[kh][3] = *reinterpret_cast<const unsigned*>(&sql[(row + 8) * QP2 + c + 8]);
    }
  }

  // ---- score: 7 n-tiles x 2 k-halves x 3 terms ----
  float sc[7][4];
#pragma unroll
  for (int t7 = 0; t7 < 7; ++t7)
#pragma unroll
    for (int e = 0; e < 4; ++e) sc[t7][e] = 0.f;
#pragma unroll
  for (int t7 = 0; t7 < 7; ++t7) {
    const int jr = t7 * 8 + g;
#pragma unroll
    for (int kh = 0; kh < 2; ++kh) {
      const int c = kh * 16 + th * 2;
      unsigned bh0 = *reinterpret_cast<const unsigned*>(&skh[jr * KP2 + c]);
      unsigned bh1 = *reinterpret_cast<const unsigned*>(&skh[jr * KP2 + c + 8]);
      unsigned bl0 = *reinterpret_cast<const unsigned*>(&skl[jr * KP2 + c]);
      unsigned bl1 = *reinterpret_cast<const unsigned*>(&skl[jr * KP2 + c + 8]);
      mma16816(sc[t7], aqh[kh], bh0, bh1);
      mma16816(sc[t7], aqh[kh], bl0, bl1);
      mma16816(sc[t7], aql[kh], bh0, bh1);
    }
  }

  // ---- bias + softmax (rows r1 = warp*16+g, r2 = r1+8) ----
  const int r1 = warp * 16 + g;
  const int r2 = r1 + 8;
  const int b1i = bidx[r1] * 13, b2i = bidx[r2] * 13;
  float m1 = -1e30f, m2 = -1e30f;
#pragma unroll
  for (int t7 = 0; t7 < 7; ++t7) {
    const int j0 = t7 * 8 + th * 2;
    const int bj0 = bidx[j0], bj1 = bidx[j0 + 1];
    sc[t7][0] += sp[b1i + bj0];
    sc[t7][1] += sp[b1i + bj1];
    sc[t7][2] += sp[b2i + bj0];
    sc[t7][3] += sp[b2i + bj1];
    m1 = fmaxf(m1, fmaxf(sc[t7][0], sc[t7][1]));
    m2 = fmaxf(m2, fmaxf(sc[t7][2], sc[t7][3]));
  }
  m1 = fmaxf(m1, __shfl_xor_sync(~0u, m1, 1));
  m1 = fmaxf(m1, __shfl_xor_sync(~0u, m1, 2));
  m2 = fmaxf(m2, __shfl_xor_sync(~0u, m2, 1));
  m2 = fmaxf(m2, __shfl_xor_sync(~0u, m2, 2));
  float s1 = 0.f, s2 = 0.f;
#pragma unroll
  for (int t7 = 0; t7 < 7; ++t7) {
    float e0 = __expf(sc[t7][0] - m1);
    float e1 = __expf(sc[t7][1] - m1);
    float e2 = __expf(sc[t7][2] - m2);
    float e3 = __expf(sc[t7][3] - m2);
    if (t7 == 6) {  // cols 48..55: only j==48 (th==0, even elem) valid
      if (th != 0) e0 = 0.f;
      e1 = 0.f;
      if (th != 0) e2 = 0.f;
      e3 = 0.f;
    }
    sc[t7][0] = e0; sc[t7][1] = e1; sc[t7][2] = e2; sc[t7][3] = e3;
    s1 += e0 + e1; s2 += e2 + e3;
  }
  s1 += __shfl_xor_sync(~0u, s1, 1); s1 += __shfl_xor_sync(~0u, s1, 2);
  s2 += __shfl_xor_sync(~0u, s2, 1); s2 += __shfl_xor_sync(~0u, s2, 2);
  const float inv1 = 1.f / s1, inv2 = 1.f / s2;
#pragma unroll
  for (int t7 = 0; t7 < 7; ++t7) {
    sc[t7][0] *= inv1; sc[t7][1] *= inv1;
    sc[t7][2] *= inv2; sc[t7][3] *= inv2;
  }

  // ---- P -> A-fragments (C layout == A layout), hi/lo split in registers ---
  unsigned ph[4][4], pl2[4][4];
#pragma unroll
  for (int s = 0; s < 3; ++s) {
    splitpack(sc[2 * s][0], sc[2 * s][1], ph[s][0], pl2[s][0]);
    splitpack(sc[2 * s][2], sc[2 * s][3], ph[s][1], pl2[s][1]);
    splitpack(sc[2 * s + 1][0], sc[2 * s + 1][1], ph[s][2], pl2[s][2]);
    splitpack(sc[2 * s + 1][2], sc[2 * s + 1][3], ph[s][3], pl2[s][3]);
  }
  splitpack(sc[6][0], sc[6][1], ph[3][0], pl2[3][0]);
  splitpack(sc[6][2], sc[6][3], ph[3][1], pl2[3][1]);
  ph[3][2] = ph[3][3] = pl2[3][2] = pl2[3][3] = 0u;

  // ---- PV: 4 n-tiles (d) x 4 k-steps (l) x 3 terms ----
  float o[4][4];
#pragma unroll
  for (int nt = 0; nt < 4; ++nt)
#pragma unroll
    for (int e = 0; e < 4; ++e) o[nt][e] = 0.f;
#pragma unroll
  for (int s = 0; s < 4; ++s) {
#pragma unroll
    for (int nt = 0; nt < 4; ++nt) {
      const int dr = nt * 8 + g;
      const int lc = s * 16 + th * 2;
      unsigned vh0 = *reinterpret_cast<const unsigned*>(&svh[dr * VP2 + lc]);
      unsigned vh1 = *reinterpret_cast<const unsigned*>(&svh[dr * VP2 + lc + 8]);
      unsigned vl0 = *reinterpret_cast<const unsigned*>(&svl[dr * VP2 + lc]);
      unsigned vl1 = *reinterpret_cast<const unsigned*>(&svl[dr * VP2 + lc + 8]);
      mma16816(o[nt], ph[s], vh0, vh1);
      mma16816(o[nt], ph[s], vl0, vl1);
      mma16816(o[nt], pl2[s], vh0, vh1);
    }
  }

  // ---- epilogue: split to bf16 hi/lo planes for gemm2 ----
  if (r1 < 49) {
    const long grow = rowbase + (r1 / 7) * 56 + (r1 % 7);
    const size_t base = (size_t)grow * 256 + head * 32;
#pragma unroll
    for (int nt = 0; nt < 4; ++nt) {
      const int d = nt * 8 + th * 2;
      unsigned hh, ll;
      splitpack(o[nt][0], o[nt][1], hh, ll);
      *reinterpret_cast<unsigned*>(&g_ath[base + d]) = hh;
      *reinterpret_cast<unsigned*>(&g_atl[base + d]) = ll;
    }
  }
  if (r2 < 49) {
    const long grow = rowbase + (r2 / 7) * 56 + (r2 % 7);
    const size_t base = (size_t)grow * 256 + head * 32;
#pragma unroll
    for (int nt = 0; nt < 4; ++nt) {
      const int d = nt * 8 + th * 2;
      unsigned hh, ll;
      splitpack(o[nt][2], o[nt][3], hh, ll);
      *reinterpret_cast<unsigned*>(&g_ath[base + d]) = hh;
      *reinterpret_cast<unsigned*>(&g_atl[base + d]) = ll;
    }
  }
}

// ---------------------------------------------------------------------------
extern "C" void kernel_launch(void* const* d_in, const int* in_sizes, int n_in,
                              void* d_out, int out_size) {
  const float* x     = (const float*)d_in[0];
  const float* pos   = (const float*)d_in[1];
  const float* w_qkv = (const float*)d_in[2];
  const float* b_qkv = (const float*)d_in[3];
  const float* w_out = (const float*)d_in[4];
  const float* b_out = (const float*)d_in[5];
  float* out = (float*)d_out;

  float* qkv_p; __nv_bfloat16 *xh, *xl, *ath, *atl, *wqh, *wql, *woh, *wol;
  cudaGetSymbolAddress((void**)&qkv_p, g_qkv);
  cudaGetSymbolAddress((void**)&xh, g_xh);
  cudaGetSymbolAddress((void**)&xl, g_xl);
  cudaGetSymbolAddress((void**)&ath, g_ath);
  cudaGetSymbolAddress((void**)&atl, g_atl);
  cudaGetSymbolAddress((void**)&wqh, g_wqh);
  cudaGetSymbolAddress((void**)&wql, g_wql);
  cudaGetSymbolAddress((void**)&woh, g_woh);
  cudaGetSymbolAddress((void**)&wol, g_wol);

  static bool attr_set = false;
  if (!attr_set) {
    cudaFuncSetAttribute(gemm_split, cudaFuncAttributeMaxDynamicSharedMemorySize,
                         NSTAGE * STAGE_B);
    attr_set = true;
  }

  // 0) split inputs to bf16 hi/lo planes
  {
    size_t n4 = (size_t)NTOK * CDIM / 4;
    split_act<<<(unsigned)((n4 + 255) / 256), 256>>>(x, xh, xl, n4);
    split_wT<<<(CDIM * QKVD + 255) / 256, 256>>>(w_qkv, wqh, wql, CDIM, QKVD);
    split_wT<<<(CDIM * CDIM + 255) / 256, 256>>>(w_out, woh, wol, CDIM, CDIM);
  }

  // 1) qkv = x @ w_qkv + b_qkv  [200704 x 768]
  {
    dim3 g(QKVD / 128, NTOK / 128);
    gemm_split<<<g, 256, NSTAGE * STAGE_B>>>(xh, xl, wqh, wql, b_qkv, qkv_p,
                                             NTOK, QKVD, CDIM);
  }

  // 2) windowed attention (tensor-core) -> att hi/lo planes
  {
    dim3 g(4096, 8);
    win_attn<<<g, 128>>>(pos);
  }

  // 3) out = att @ w_out + b_out  [200704 x 256]
  {
    dim3 g(CDIM / 128, NTOK / 128);
    gemm_split<<<g, 256, NSTAGE * STAGE_B>>>(ath, atl, woh, wol, b_out, out,
                                             NTOK, CDIM, CDIM);
  }
}